// round 12
// baseline (speedup 1.0000x reference)
#include <cuda_runtime.h>
#include <cuda_bf16.h>
#include <cuda_fp16.h>
#include <math.h>
#include <stdint.h>

#define NNODES 50000
#define NEDGES 800000
#define HC 128
#define INV_SQRT_C 0.1767766952966369f

#define SB 512
#define NSB ((NNODES + SB - 1) / SB)   // 98

// ---------------- scratch (device globals: allocation-free) ----------------
__device__ float          g_q[NNODES * HC];
__device__ __nv_bfloat16  g_kh[NNODES * HC];
__device__ __nv_bfloat16  g_vh[NNODES * HC];
__device__ float          g_h[NNODES * HC];
__device__ int   g_cnt[NNODES];
__device__ int   g_fill[NNODES];
__device__ int   g_rowptr[NNODES + 1];
__device__ volatile int g_scan_incl[NSB];
__device__ volatile int g_scan_flag[NSB];
__device__ int2  g_se[NEDGES];      // packed (src, edge_weight-as-bits)
__device__ int   g_is32;            // 1 => edge_index is int32, 0 => int64

// ---------------- init: zero counts/flags + dtype detection ----------------
// If edge_index is int64 (values < 2^31), every odd 32-bit word in the first
// NEDGES words is a zero high-half. If int32, those words are random node ids.
__global__ void init_kernel(const unsigned int* __restrict__ w) {
    int i = blockIdx.x * blockDim.x + threadIdx.x;
    if (i < NNODES) { g_cnt[i] = 0; g_fill[i] = 0; }
    if (i < NSB)    { g_scan_flag[i] = 0; }
    if (i == 0)     { g_is32 = 0; }
    int idx = 2 * i + 1;
    unsigned int nz = (idx < NEDGES && w[idx] != 0u) ? 1u : 0u;
    if (__ballot_sync(0xffffffffu, nz) && (threadIdx.x & 31) == 0)
        g_is32 = 1;
}

__device__ __forceinline__ int load_idx(const void* ei, int pos, int is32) {
    long long v;
    if (is32) v = ((const int*)ei)[pos];
    else      v = ((const long long*)ei)[pos];
    int iv = (int)v;
    if (iv < 0) iv = 0;
    if (iv >= NNODES) iv = NNODES - 1;
    return iv;
}

__global__ void hist_kernel(const void* __restrict__ ei) {
    int e = blockIdx.x * blockDim.x + threadIdx.x;
    if (e >= NEDGES) return;
    int is32 = g_is32;
    int d = load_idx(ei, NEDGES + e, is32);
    atomicAdd(&g_cnt[d], 1);
}

// ------- single-kernel chained inter-block scan: g_cnt -> g_rowptr ---------
// 98 blocks (all resident on 148 SMs simultaneously -> chain cannot deadlock)
__global__ void scan_chain_kernel() {
    __shared__ int s[SB];
    __shared__ int s_prev;
    int tid = threadIdx.x;
    int bid = blockIdx.x;
    int i = bid * SB + tid;
    int v = (i < NNODES) ? g_cnt[i] : 0;
    s[tid] = v;
    __syncthreads();
    #pragma unroll
    for (int off = 1; off < SB; off <<= 1) {
        int t = (tid >= off) ? s[tid - off] : 0;
        __syncthreads();
        s[tid] += t;
        __syncthreads();
    }
    if (tid == 0) {
        int prev = 0;
        if (bid > 0) {
            while (g_scan_flag[bid - 1] == 0) { }
            __threadfence();
            prev = g_scan_incl[bid - 1];
        }
        g_scan_incl[bid] = prev + s[SB - 1];
        __threadfence();
        g_scan_flag[bid] = 1;
        s_prev = prev;
    }
    __syncthreads();
    int prev = s_prev;
    if (i < NNODES) g_rowptr[i + 1] = prev + s[tid];
    if (i == 0) g_rowptr[0] = 0;
}

__global__ void scatter_kernel(const void* __restrict__ ei,
                               const float* __restrict__ ew) {
    int e = blockIdx.x * blockDim.x + threadIdx.x;
    if (e >= NEDGES) return;
    int is32 = g_is32;
    int s = load_idx(ei, e, is32);
    int d = load_idx(ei, NEDGES + e, is32);
    int pos = g_rowptr[d] + atomicAdd(&g_fill[d], 1);
    g_se[pos] = make_int2(s, __float_as_int(ew[e]));
}

// ---------------- fused 4-way GEMM via fp16 mma m16n8k16 -------------------
// BM=128, BN=128, BK=16, double-buffered smem, 8 warps, warp tile 64x32.
// A/B stored as half2 packed along k: As2[k/2][m], Bs2[k/2][n], pad 136
// (bank = 8c + r + const -> conflict-free fragment loads).
#define GPAD 136

__device__ __forceinline__ unsigned int h2u(float a, float b) {
    __half2 h = __floats2half2_rn(a, b);
    return *reinterpret_cast<unsigned int*>(&h);
}

__global__ __launch_bounds__(256, 2) void gemm4_fp16_kernel(
    const float* __restrict__ Xp, int xFromH,
    const float* __restrict__ Wq, const float* __restrict__ Wk,
    const float* __restrict__ Wv, const float* __restrict__ Ws,
    const float* __restrict__ bq, const float* __restrict__ bk,
    const float* __restrict__ bv, const float* __restrict__ bs,
    float* __restrict__ Op, int outToH)
{
    const float* X = xFromH ? g_h : Xp;
    const float* W; const float* B;
    float* O = nullptr;
    __nv_bfloat16* OH = nullptr;
    int mm = blockIdx.y;
    if      (mm == 0) { W = Wq; B = bq; O = g_q; }
    else if (mm == 1) { W = Wk; B = bk; OH = g_kh; }
    else if (mm == 2) { W = Wv; B = bv; OH = g_vh; }
    else              { W = Ws; B = bs; O = outToH ? g_h : Op; }

    __shared__ unsigned int As2[2][8][GPAD];   // [buf][k2][m], half2 = {k, k+1}
    __shared__ unsigned int Bs2[2][8][GPAD];   // [buf][k2][n]

    int tid  = threadIdx.x;
    int warp = tid >> 5;
    int lane = tid & 31;
    int r = lane >> 2;          // 0..7  (group id)
    int c = lane & 3;           // 0..3  (thread-in-group)
    int warp_m = (warp >> 2) * 64;
    int warp_n = (warp & 3) * 32;
    int mbase = blockIdx.x * 128;

    float acc[4][4][4];
    #pragma unroll
    for (int mi = 0; mi < 4; mi++)
        #pragma unroll
        for (int ni = 0; ni < 4; ni++)
            #pragma unroll
            for (int q = 0; q < 4; q++) acc[mi][ni][q] = 0.f;

    int m_a   = tid >> 1;
    int row_a = mbase + m_a;
    int kq    = (tid & 1);
    const float4* Xv = (const float4*)X;       // row stride 32 float4
    bool arow_ok = (row_a < NNODES);
    int k2b = tid >> 5;
    int n4  = (tid & 31) * 4;

    float4 ra0, ra1, rb0, rb1;

    // prologue: load tile 0
    {
        ra0 = ra1 = make_float4(0.f, 0.f, 0.f, 0.f);
        if (arow_ok) {
            ra0 = Xv[row_a * 32 + kq];
            ra1 = Xv[row_a * 32 + 2 + kq];
        }
        rb0 = *(const float4*)(W + (2 * k2b)     * 128 + n4);
        rb1 = *(const float4*)(W + (2 * k2b + 1) * 128 + n4);
    }
    {
        int k2a = kq * 2;
        As2[0][k2a + 0][m_a] = h2u(ra0.x, ra0.y);
        As2[0][k2a + 1][m_a] = h2u(ra0.z, ra0.w);
        As2[0][k2a + 4][m_a] = h2u(ra1.x, ra1.y);
        As2[0][k2a + 5][m_a] = h2u(ra1.z, ra1.w);
        uint4 bu = make_uint4(h2u(rb0.x, rb1.x), h2u(rb0.y, rb1.y),
                              h2u(rb0.z, rb1.z), h2u(rb0.w, rb1.w));
        *(uint4*)&Bs2[0][k2b][n4] = bu;
    }
    __syncthreads();

    #pragma unroll
    for (int kt = 0; kt < 8; kt++) {
        int cur = kt & 1;
        int nxt = cur ^ 1;
        if (kt < 7) {
            int k0 = (kt + 1) * 16;
            ra0 = ra1 = make_float4(0.f, 0.f, 0.f, 0.f);
            if (arow_ok) {
                ra0 = Xv[row_a * 32 + k0 / 4 + kq];
                ra1 = Xv[row_a * 32 + k0 / 4 + 2 + kq];
            }
            rb0 = *(const float4*)(W + (k0 + 2 * k2b)     * 128 + n4);
            rb1 = *(const float4*)(W + (k0 + 2 * k2b + 1) * 128 + n4);
        }
        {
            unsigned int af[4][4];
            #pragma unroll
            for (int mi = 0; mi < 4; mi++) {
                int bm = warp_m + mi * 16;
                af[mi][0] = As2[cur][c][bm + r];
                af[mi][1] = As2[cur][c][bm + r + 8];
                af[mi][2] = As2[cur][c + 4][bm + r];
                af[mi][3] = As2[cur][c + 4][bm + r + 8];
            }
            unsigned int bf[4][2];
            #pragma unroll
            for (int ni = 0; ni < 4; ni++) {
                int bn = warp_n + ni * 8;
                bf[ni][0] = Bs2[cur][c][bn + r];
                bf[ni][1] = Bs2[cur][c + 4][bn + r];
            }
            #pragma unroll
            for (int mi = 0; mi < 4; mi++)
                #pragma unroll
                for (int ni = 0; ni < 4; ni++) {
                    asm volatile(
                        "mma.sync.aligned.m16n8k16.row.col.f32.f16.f16.f32 "
                        "{%0,%1,%2,%3}, {%4,%5,%6,%7}, {%8,%9}, {%0,%1,%2,%3};"
                        : "+f"(acc[mi][ni][0]), "+f"(acc[mi][ni][1]),
                          "+f"(acc[mi][ni][2]), "+f"(acc[mi][ni][3])
                        : "r"(af[mi][0]), "r"(af[mi][1]),
                          "r"(af[mi][2]), "r"(af[mi][3]),
                          "r"(bf[ni][0]), "r"(bf[ni][1]));
                }
        }
        if (kt < 7) {
            int k2a = kq * 2;
            As2[nxt][k2a + 0][m_a] = h2u(ra0.x, ra0.y);
            As2[nxt][k2a + 1][m_a] = h2u(ra0.z, ra0.w);
            As2[nxt][k2a + 4][m_a] = h2u(ra1.x, ra1.y);
            As2[nxt][k2a + 5][m_a] = h2u(ra1.z, ra1.w);
            uint4 bu = make_uint4(h2u(rb0.x, rb1.x), h2u(rb0.y, rb1.y),
                                  h2u(rb0.z, rb1.z), h2u(rb0.w, rb1.w));
            *(uint4*)&Bs2[nxt][k2b][n4] = bu;
        }
        __syncthreads();
    }

    // ---- epilogue: + bias, store (fp32 for q/skip, bf16 for k/v) ----
    #pragma unroll
    for (int ni = 0; ni < 4; ni++) {
        int col = warp_n + ni * 8 + c * 2;
        float b0 = B[col];
        float b1 = B[col + 1];
        #pragma unroll
        for (int mi = 0; mi < 4; mi++) {
            int row0 = mbase + warp_m + mi * 16 + r;
            int row1 = row0 + 8;
            if (OH) {
                if (row0 < NNODES)
                    ((__nv_bfloat162*)OH)[row0 * 64 + col / 2] =
                        __float22bfloat162_rn(make_float2(acc[mi][ni][0] + b0,
                                                          acc[mi][ni][1] + b1));
                if (row1 < NNODES)
                    ((__nv_bfloat162*)OH)[row1 * 64 + col / 2] =
                        __float22bfloat162_rn(make_float2(acc[mi][ni][2] + b0,
                                                          acc[mi][ni][3] + b1));
            } else {
                if (row0 < NNODES) {
                    float2 o = make_float2(acc[mi][ni][0] + b0, acc[mi][ni][1] + b1);
                    *(float2*)&O[row0 * 128 + col] = o;
                }
                if (row1 < NNODES) {
                    float2 o = make_float2(acc[mi][ni][2] + b0, acc[mi][ni][3] + b1);
                    *(float2*)&O[row1 * 128 + col] = o;
                }
            }
        }
    }
}

// ---------------- edge aggregation (R9 form): warp/node, online softmax ----
__device__ __forceinline__ float2 bfu2f(unsigned int u) {
    __nv_bfloat162 b = *reinterpret_cast<__nv_bfloat162*>(&u);
    return __bfloat1622float2(b);
}

__device__ __forceinline__ void online_update(
    float alpha, float ew, const float4& vv, const float4& wev,
    float& m, float& d, float4& acc)
{
    float delta = alpha - m;
    float e = __expf(0.f - fabsf(delta));
    bool up = delta > 0.f;
    float p    = up ? 1.f : e;
    float corr = up ? e : 1.f;
    m = fmaxf(m, alpha);
    d = fmaf(d, corr, p);
    float vjx = fmaf(ew, wev.x, vv.x);
    float vjy = fmaf(ew, wev.y, vv.y);
    float vjz = fmaf(ew, wev.z, vv.z);
    float vjw = fmaf(ew, wev.w, vv.w);
    acc.x = fmaf(p, vjx, acc.x * corr);
    acc.y = fmaf(p, vjy, acc.y * corr);
    acc.z = fmaf(p, vjz, acc.z * corr);
    acc.w = fmaf(p, vjw, acc.w * corr);
}

__global__ __launch_bounds__(256) void edge_kernel(
    const float* __restrict__ We, float* __restrict__ Op, int outToH)
{
    float* out = outToH ? g_h : Op;
    int node = blockIdx.x * 8 + (threadIdx.x >> 5);
    if (node >= NNODES) return;
    int lane = threadIdx.x & 31;

    float4 qv  = ((const float4*)g_q)[node * 32 + lane];
    float4 wev = ((const float4*)We)[lane];

    float t = qv.x * wev.x + qv.y * wev.y + qv.z * wev.z + qv.w * wev.w;
    t += __shfl_xor_sync(0xffffffffu, t, 1);
    t += __shfl_xor_sync(0xffffffffu, t, 2);
    t += __shfl_xor_sync(0xffffffffu, t, 4);
    float qWe_h = t;

    const uint2* Kh = (const uint2*)g_kh;
    const uint2* Vh = (const uint2*)g_vh;

    int beg = g_rowptr[node];
    int end = g_rowptr[node + 1];

    float m = -3.0e38f;
    float d = 0.f;
    float4 acc = make_float4(0.f, 0.f, 0.f, 0.f);

    int j = beg;
    int n4 = beg + ((end - beg) & ~3);
    for (; j < n4; j += 4) {
        int2 e0 = g_se[j],     e1 = g_se[j + 1];
        int2 e2 = g_se[j + 2], e3 = g_se[j + 3];
        uint2 ku0 = Kh[e0.x * 32 + lane], ku1 = Kh[e1.x * 32 + lane];
        uint2 ku2 = Kh[e2.x * 32 + lane], ku3 = Kh[e3.x * 32 + lane];
        uint2 vu0 = Vh[e0.x * 32 + lane], vu1 = Vh[e1.x * 32 + lane];
        uint2 vu2 = Vh[e2.x * 32 + lane], vu3 = Vh[e3.x * 32 + lane];
        float ew0 = __int_as_float(e0.y), ew1 = __int_as_float(e1.y);
        float ew2 = __int_as_float(e2.y), ew3 = __int_as_float(e3.y);

        float2 a0 = bfu2f(ku0.x), b0 = bfu2f(ku0.y);
        float2 a1 = bfu2f(ku1.x), b1 = bfu2f(ku1.y);
        float2 a2 = bfu2f(ku2.x), b2 = bfu2f(ku2.y);
        float2 a3 = bfu2f(ku3.x), b3 = bfu2f(ku3.y);
        float p40 = qv.x * a0.x + qv.y * a0.y + qv.z * b0.x + qv.w * b0.y;
        float p41 = qv.x * a1.x + qv.y * a1.y + qv.z * b1.x + qv.w * b1.y;
        float p42 = qv.x * a2.x + qv.y * a2.y + qv.z * b2.x + qv.w * b2.y;
        float p43 = qv.x * a3.x + qv.y * a3.y + qv.z * b3.x + qv.w * b3.y;
        p40 += __shfl_xor_sync(0xffffffffu, p40, 1);
        p41 += __shfl_xor_sync(0xffffffffu, p41, 1);
        p42 += __shfl_xor_sync(0xffffffffu, p42, 1);
        p43 += __shfl_xor_sync(0xffffffffu, p43, 1);
        p40 += __shfl_xor_sync(0xffffffffu, p40, 2);
        p41 += __shfl_xor_sync(0xffffffffu, p41, 2);
        p42 += __shfl_xor_sync(0xffffffffu, p42, 2);
        p43 += __shfl_xor_sync(0xffffffffu, p43, 2);
        p40 += __shfl_xor_sync(0xffffffffu, p40, 4);
        p41 += __shfl_xor_sync(0xffffffffu, p41, 4);
        p42 += __shfl_xor_sync(0xffffffffu, p42, 4);
        p43 += __shfl_xor_sync(0xffffffffu, p43, 4);
        float al0 = fmaf(ew0, qWe_h, p40) * INV_SQRT_C;
        float al1 = fmaf(ew1, qWe_h, p41) * INV_SQRT_C;
        float al2 = fmaf(ew2, qWe_h, p42) * INV_SQRT_C;
        float al3 = fmaf(ew3, qWe_h, p43) * INV_SQRT_C;

        float2 w0a = bfu2f(vu0.x), w0b = bfu2f(vu0.y);
        float2 w1a = bfu2f(vu1.x), w1b = bfu2f(vu1.y);
        float2 w2a = bfu2f(vu2.x), w2b = bfu2f(vu2.y);
        float2 w3a = bfu2f(vu3.x), w3b = bfu2f(vu3.y);
        online_update(al0, ew0, make_float4(w0a.x, w0a.y, w0b.x, w0b.y), wev, m, d, acc);
        online_update(al1, ew1, make_float4(w1a.x, w1a.y, w1b.x, w1b.y), wev, m, d, acc);
        online_update(al2, ew2, make_float4(w2a.x, w2a.y, w2b.x, w2b.y), wev, m, d, acc);
        online_update(al3, ew3, make_float4(w3a.x, w3a.y, w3b.x, w3b.y), wev, m, d, acc);
    }
    for (; j < end; ++j) {
        int2 e0 = g_se[j];
        float ew0 = __int_as_float(e0.y);
        uint2 ku0 = Kh[e0.x * 32 + lane];
        uint2 vu0 = Vh[e0.x * 32 + lane];
        float2 k0a = bfu2f(ku0.x), k0b = bfu2f(ku0.y);
        float p40 = qv.x * k0a.x + qv.y * k0a.y + qv.z * k0b.x + qv.w * k0b.y;
        p40 += __shfl_xor_sync(0xffffffffu, p40, 1);
        p40 += __shfl_xor_sync(0xffffffffu, p40, 2);
        p40 += __shfl_xor_sync(0xffffffffu, p40, 4);
        float al0 = fmaf(ew0, qWe_h, p40) * INV_SQRT_C;
        float2 v0a = bfu2f(vu0.x), v0b = bfu2f(vu0.y);
        online_update(al0, ew0, make_float4(v0a.x, v0a.y, v0b.x, v0b.y), wev, m, d, acc);
    }

    float invd = (d > 0.f) ? (1.f / d) : 0.f;
    float4* op = (float4*)out + node * 32 + lane;
    float4 cur = *op;
    cur.x += acc.x * invd;
    cur.y += acc.y * invd;
    cur.z += acc.z * invd;
    cur.w += acc.w * invd;
    *op = cur;
}

// ---------------- launch ---------------------------------------------------
// Launch order puts edge_kernel at position 6 so the fixed ncu window
// (-s 5 -c 1) finally profiles it: init(1), hist(2), scan(3), scatter(4),
// gemm1(5, CSR-independent), edge1(6), gemm2(7), edge2(8).
extern "C" void kernel_launch(void* const* d_in, const int* in_sizes, int n_in,
                              void* d_out, int out_size)
{
    (void)in_sizes; (void)n_in; (void)out_size;
    const float* x    = (const float*)d_in[0];
    const float* ewt  = (const float*)d_in[1];
    const float* Wq1  = (const float*)d_in[2];
    const float* bq1  = (const float*)d_in[3];
    const float* Wk1  = (const float*)d_in[4];
    const float* bk1  = (const float*)d_in[5];
    const float* Wv1  = (const float*)d_in[6];
    const float* bv1  = (const float*)d_in[7];
    const float* We1  = (const float*)d_in[8];
    const float* Ws1  = (const float*)d_in[9];
    const float* bs1  = (const float*)d_in[10];
    const float* Wq2  = (const float*)d_in[11];
    const float* bq2  = (const float*)d_in[12];
    const float* Wk2  = (const float*)d_in[13];
    const float* bk2  = (const float*)d_in[14];
    const float* Wv2  = (const float*)d_in[15];
    const float* bv2  = (const float*)d_in[16];
    const float* We2  = (const float*)d_in[17];
    const float* Ws2  = (const float*)d_in[18];
    const float* bs2  = (const float*)d_in[19];
    const void* ei    = d_in[20];
    float* out = (float*)d_out;

    dim3 ggrid((NNODES + 127) / 128, 4);
    dim3 egrid((NNODES + 7) / 8);

    init_kernel<<<(NEDGES / 2 + 255) / 256, 256>>>((const unsigned int*)ei);
    hist_kernel<<<(NEDGES + 255) / 256, 256>>>(ei);
    scan_chain_kernel<<<NSB, SB>>>();
    scatter_kernel<<<(NEDGES + 255) / 256, 256>>>(ei, ewt);

    // layer 1 (gemm1 is CSR-independent; placed 5th so edge1 is launch #6)
    gemm4_fp16_kernel<<<ggrid, 256>>>(x, 0, Wq1, Wk1, Wv1, Ws1,
                                      bq1, bk1, bv1, bs1, nullptr, 1);
    edge_kernel<<<egrid, 256>>>(We1, nullptr, 1);

    // layer 2
    gemm4_fp16_kernel<<<ggrid, 256>>>(nullptr, 1, Wq2, Wk2, Wv2, Ws2,
                                      bq2, bk2, bv2, bs2, out, 0);
    edge_kernel<<<egrid, 256>>>(We2, out, 0);
}

// round 13
// speedup vs baseline: 1.3911x; 1.3911x over previous
#include <cuda_runtime.h>
#include <cuda_bf16.h>
#include <cuda_fp16.h>
#include <math.h>
#include <stdint.h>

#define NNODES 50000
#define NEDGES 800000
#define HC 128
#define INV_SQRT_C 0.1767766952966369f

#define SB 512
#define NSB ((NNODES + SB - 1) / SB)   // 98

// ---------------- scratch (device globals: allocation-free) ----------------
__device__ float          g_q[NNODES * HC];
__device__ __nv_bfloat16  g_kh[NNODES * HC];
__device__ __nv_bfloat16  g_vh[NNODES * HC];
__device__ float          g_h[NNODES * HC];
__device__ int   g_cnt[NNODES];
__device__ int   g_fill[NNODES];
__device__ int   g_rowptr[NNODES + 1];
__device__ int   g_bsum[NSB];
__device__ int2  g_se[NEDGES];      // packed (src, edge_weight-as-bits)
__device__ int   g_is32;            // 1 => edge_index is int32, 0 => int64

// ---------------- init: zero counts + dtype detection ----------------------
// If edge_index is int64 (values < 2^31), every odd 32-bit word in the first
// NEDGES words is a zero high-half. If int32, those words are random node ids.
__global__ void init_kernel(const unsigned int* __restrict__ w) {
    int i = blockIdx.x * blockDim.x + threadIdx.x;
    if (i < NNODES) { g_cnt[i] = 0; g_fill[i] = 0; }
    if (i == 0)     { g_is32 = 0; }
    int idx = 2 * i + 1;
    unsigned int nz = (idx < NEDGES && w[idx] != 0u) ? 1u : 0u;
    if (__ballot_sync(0xffffffffu, nz) && (threadIdx.x & 31) == 0)
        g_is32 = 1;
}

__device__ __forceinline__ int load_idx(const void* ei, int pos, int is32) {
    long long v;
    if (is32) v = ((const int*)ei)[pos];
    else      v = ((const long long*)ei)[pos];
    int iv = (int)v;
    if (iv < 0) iv = 0;
    if (iv >= NNODES) iv = NNODES - 1;
    return iv;
}

__global__ void hist_kernel(const void* __restrict__ ei) {
    int e = blockIdx.x * blockDim.x + threadIdx.x;
    if (e >= NEDGES) return;
    int is32 = g_is32;
    int d = load_idx(ei, NEDGES + e, is32);
    atomicAdd(&g_cnt[d], 1);
}

// ------- parallel prefix sum over g_cnt -> g_rowptr (3 small kernels) ------
__global__ void scan_blocks_kernel() {
    __shared__ int s[SB];
    int tid = threadIdx.x;
    int i = blockIdx.x * SB + tid;
    int v = (i < NNODES) ? g_cnt[i] : 0;
    s[tid] = v;
    __syncthreads();
    #pragma unroll
    for (int off = 1; off < SB; off <<= 1) {
        int t = (tid >= off) ? s[tid - off] : 0;
        __syncthreads();
        s[tid] += t;
        __syncthreads();
    }
    if (i < NNODES) g_rowptr[i + 1] = s[tid];
    if (tid == SB - 1) g_bsum[blockIdx.x] = s[tid];
}

__global__ void scan_tops_kernel() {   // 1 block, 128 threads, NSB<=128
    __shared__ int s[128];
    int tid = threadIdx.x;
    int v = (tid < NSB) ? g_bsum[tid] : 0;
    s[tid] = v;
    __syncthreads();
    #pragma unroll
    for (int off = 1; off < 128; off <<= 1) {
        int t = (tid >= off) ? s[tid - off] : 0;
        __syncthreads();
        s[tid] += t;
        __syncthreads();
    }
    if (tid < NSB) g_bsum[tid] = s[tid] - v;   // exclusive
}

__global__ void scan_add_kernel() {
    int i = blockIdx.x * SB + threadIdx.x;
    if (i < NNODES) g_rowptr[i + 1] += g_bsum[blockIdx.x];
    if (i == 0) g_rowptr[0] = 0;
}

__global__ void scatter_kernel(const void* __restrict__ ei,
                               const float* __restrict__ ew) {
    int e = blockIdx.x * blockDim.x + threadIdx.x;
    if (e >= NEDGES) return;
    int is32 = g_is32;
    int s = load_idx(ei, e, is32);
    int d = load_idx(ei, NEDGES + e, is32);
    int pos = g_rowptr[d] + atomicAdd(&g_fill[d], 1);
    g_se[pos] = make_int2(s, __float_as_int(ew[e]));
}

// ---------------- fused 4-way GEMM via fp16 mma m16n8k16 -------------------
// BM=128, BN=128, BK=16, double-buffered smem, 8 warps, warp tile 64x32.
// A/B stored as half2 packed along k: As2[k/2][m], Bs2[k/2][n], pad 136
// (bank = 8c + r + const -> conflict-free fragment loads).
#define GPAD 136

__device__ __forceinline__ unsigned int h2u(float a, float b) {
    __half2 h = __floats2half2_rn(a, b);
    return *reinterpret_cast<unsigned int*>(&h);
}

__global__ __launch_bounds__(256, 2) void gemm4_fp16_kernel(
    const float* __restrict__ Xp, int xFromH,
    const float* __restrict__ Wq, const float* __restrict__ Wk,
    const float* __restrict__ Wv, const float* __restrict__ Ws,
    const float* __restrict__ bq, const float* __restrict__ bk,
    const float* __restrict__ bv, const float* __restrict__ bs,
    float* __restrict__ Op, int outToH)
{
    const float* X = xFromH ? g_h : Xp;
    const float* W; const float* B;
    float* O = nullptr;
    __nv_bfloat16* OH = nullptr;
    int mm = blockIdx.y;
    if      (mm == 0) { W = Wq; B = bq; O = g_q; }
    else if (mm == 1) { W = Wk; B = bk; OH = g_kh; }
    else if (mm == 2) { W = Wv; B = bv; OH = g_vh; }
    else              { W = Ws; B = bs; O = outToH ? g_h : Op; }

    __shared__ unsigned int As2[2][8][GPAD];   // [buf][k2][m], half2 = {k, k+1}
    __shared__ unsigned int Bs2[2][8][GPAD];   // [buf][k2][n]

    int tid  = threadIdx.x;
    int warp = tid >> 5;
    int lane = tid & 31;
    int r = lane >> 2;          // 0..7  (group id)
    int c = lane & 3;           // 0..3  (thread-in-group)
    int warp_m = (warp >> 2) * 64;
    int warp_n = (warp & 3) * 32;
    int mbase = blockIdx.x * 128;

    float acc[4][4][4];
    #pragma unroll
    for (int mi = 0; mi < 4; mi++)
        #pragma unroll
        for (int ni = 0; ni < 4; ni++)
            #pragma unroll
            for (int q = 0; q < 4; q++) acc[mi][ni][q] = 0.f;

    int m_a   = tid >> 1;
    int row_a = mbase + m_a;
    int kq    = (tid & 1);
    const float4* Xv = (const float4*)X;       // row stride 32 float4
    bool arow_ok = (row_a < NNODES);
    int k2b = tid >> 5;
    int n4  = (tid & 31) * 4;

    float4 ra0, ra1, rb0, rb1;

    // prologue: load tile 0
    {
        ra0 = ra1 = make_float4(0.f, 0.f, 0.f, 0.f);
        if (arow_ok) {
            ra0 = Xv[row_a * 32 + kq];
            ra1 = Xv[row_a * 32 + 2 + kq];
        }
        rb0 = *(const float4*)(W + (2 * k2b)     * 128 + n4);
        rb1 = *(const float4*)(W + (2 * k2b + 1) * 128 + n4);
    }
    {
        int k2a = kq * 2;
        As2[0][k2a + 0][m_a] = h2u(ra0.x, ra0.y);
        As2[0][k2a + 1][m_a] = h2u(ra0.z, ra0.w);
        As2[0][k2a + 4][m_a] = h2u(ra1.x, ra1.y);
        As2[0][k2a + 5][m_a] = h2u(ra1.z, ra1.w);
        uint4 bu = make_uint4(h2u(rb0.x, rb1.x), h2u(rb0.y, rb1.y),
                              h2u(rb0.z, rb1.z), h2u(rb0.w, rb1.w));
        *(uint4*)&Bs2[0][k2b][n4] = bu;
    }
    __syncthreads();

    #pragma unroll
    for (int kt = 0; kt < 8; kt++) {
        int cur = kt & 1;
        int nxt = cur ^ 1;
        if (kt < 7) {
            int k0 = (kt + 1) * 16;
            ra0 = ra1 = make_float4(0.f, 0.f, 0.f, 0.f);
            if (arow_ok) {
                ra0 = Xv[row_a * 32 + k0 / 4 + kq];
                ra1 = Xv[row_a * 32 + k0 / 4 + 2 + kq];
            }
            rb0 = *(const float4*)(W + (k0 + 2 * k2b)     * 128 + n4);
            rb1 = *(const float4*)(W + (k0 + 2 * k2b + 1) * 128 + n4);
        }
        {
            unsigned int af[4][4];
            #pragma unroll
            for (int mi = 0; mi < 4; mi++) {
                int bm = warp_m + mi * 16;
                af[mi][0] = As2[cur][c][bm + r];
                af[mi][1] = As2[cur][c][bm + r + 8];
                af[mi][2] = As2[cur][c + 4][bm + r];
                af[mi][3] = As2[cur][c + 4][bm + r + 8];
            }
            unsigned int bf[4][2];
            #pragma unroll
            for (int ni = 0; ni < 4; ni++) {
                int bn = warp_n + ni * 8;
                bf[ni][0] = Bs2[cur][c][bn + r];
                bf[ni][1] = Bs2[cur][c + 4][bn + r];
            }
            #pragma unroll
            for (int mi = 0; mi < 4; mi++)
                #pragma unroll
                for (int ni = 0; ni < 4; ni++) {
                    asm volatile(
                        "mma.sync.aligned.m16n8k16.row.col.f32.f16.f16.f32 "
                        "{%0,%1,%2,%3}, {%4,%5,%6,%7}, {%8,%9}, {%0,%1,%2,%3};"
                        : "+f"(acc[mi][ni][0]), "+f"(acc[mi][ni][1]),
                          "+f"(acc[mi][ni][2]), "+f"(acc[mi][ni][3])
                        : "r"(af[mi][0]), "r"(af[mi][1]),
                          "r"(af[mi][2]), "r"(af[mi][3]),
                          "r"(bf[ni][0]), "r"(bf[ni][1]));
                }
        }
        if (kt < 7) {
            int k2a = kq * 2;
            As2[nxt][k2a + 0][m_a] = h2u(ra0.x, ra0.y);
            As2[nxt][k2a + 1][m_a] = h2u(ra0.z, ra0.w);
            As2[nxt][k2a + 4][m_a] = h2u(ra1.x, ra1.y);
            As2[nxt][k2a + 5][m_a] = h2u(ra1.z, ra1.w);
            uint4 bu = make_uint4(h2u(rb0.x, rb1.x), h2u(rb0.y, rb1.y),
                                  h2u(rb0.z, rb1.z), h2u(rb0.w, rb1.w));
            *(uint4*)&Bs2[nxt][k2b][n4] = bu;
        }
        __syncthreads();
    }

    // ---- epilogue: + bias, store (fp32 for q/skip, bf16 for k/v) ----
    #pragma unroll
    for (int ni = 0; ni < 4; ni++) {
        int col = warp_n + ni * 8 + c * 2;
        float b0 = B[col];
        float b1 = B[col + 1];
        #pragma unroll
        for (int mi = 0; mi < 4; mi++) {
            int row0 = mbase + warp_m + mi * 16 + r;
            int row1 = row0 + 8;
            if (OH) {
                if (row0 < NNODES)
                    ((__nv_bfloat162*)OH)[row0 * 64 + col / 2] =
                        __float22bfloat162_rn(make_float2(acc[mi][ni][0] + b0,
                                                          acc[mi][ni][1] + b1));
                if (row1 < NNODES)
                    ((__nv_bfloat162*)OH)[row1 * 64 + col / 2] =
                        __float22bfloat162_rn(make_float2(acc[mi][ni][2] + b0,
                                                          acc[mi][ni][3] + b1));
            } else {
                if (row0 < NNODES) {
                    float2 o = make_float2(acc[mi][ni][0] + b0, acc[mi][ni][1] + b1);
                    *(float2*)&O[row0 * 128 + col] = o;
                }
                if (row1 < NNODES) {
                    float2 o = make_float2(acc[mi][ni][2] + b0, acc[mi][ni][3] + b1);
                    *(float2*)&O[row1 * 128 + col] = o;
                }
            }
        }
    }
}

// ---------------- edge aggregation (R9 form): warp/node, online softmax ----
__device__ __forceinline__ float2 bfu2f(unsigned int u) {
    __nv_bfloat162 b = *reinterpret_cast<__nv_bfloat162*>(&u);
    return __bfloat1622float2(b);
}

__device__ __forceinline__ void online_update(
    float alpha, float ew, const float4& vv, const float4& wev,
    float& m, float& d, float4& acc)
{
    float delta = alpha - m;
    float e = __expf(0.f - fabsf(delta));
    bool up = delta > 0.f;
    float p    = up ? 1.f : e;
    float corr = up ? e : 1.f;
    m = fmaxf(m, alpha);
    d = fmaf(d, corr, p);
    float vjx = fmaf(ew, wev.x, vv.x);
    float vjy = fmaf(ew, wev.y, vv.y);
    float vjz = fmaf(ew, wev.z, vv.z);
    float vjw = fmaf(ew, wev.w, vv.w);
    acc.x = fmaf(p, vjx, acc.x * corr);
    acc.y = fmaf(p, vjy, acc.y * corr);
    acc.z = fmaf(p, vjz, acc.z * corr);
    acc.w = fmaf(p, vjw, acc.w * corr);
}

__global__ __launch_bounds__(256) void edge_kernel(
    const float* __restrict__ We, float* __restrict__ Op, int outToH)
{
    float* out = outToH ? g_h : Op;
    int node = blockIdx.x * 8 + (threadIdx.x >> 5);
    if (node >= NNODES) return;
    int lane = threadIdx.x & 31;

    float4 qv  = ((const float4*)g_q)[node * 32 + lane];
    float4 wev = ((const float4*)We)[lane];

    float t = qv.x * wev.x + qv.y * wev.y + qv.z * wev.z + qv.w * wev.w;
    t += __shfl_xor_sync(0xffffffffu, t, 1);
    t += __shfl_xor_sync(0xffffffffu, t, 2);
    t += __shfl_xor_sync(0xffffffffu, t, 4);
    float qWe_h = t;

    const uint2* Kh = (const uint2*)g_kh;
    const uint2* Vh = (const uint2*)g_vh;

    int beg = g_rowptr[node];
    int end = g_rowptr[node + 1];

    float m = -3.0e38f;
    float d = 0.f;
    float4 acc = make_float4(0.f, 0.f, 0.f, 0.f);

    int j = beg;
    int n4 = beg + ((end - beg) & ~3);
    for (; j < n4; j += 4) {
        int2 e0 = g_se[j],     e1 = g_se[j + 1];
        int2 e2 = g_se[j + 2], e3 = g_se[j + 3];
        uint2 ku0 = Kh[e0.x * 32 + lane], ku1 = Kh[e1.x * 32 + lane];
        uint2 ku2 = Kh[e2.x * 32 + lane], ku3 = Kh[e3.x * 32 + lane];
        uint2 vu0 = Vh[e0.x * 32 + lane], vu1 = Vh[e1.x * 32 + lane];
        uint2 vu2 = Vh[e2.x * 32 + lane], vu3 = Vh[e3.x * 32 + lane];
        float ew0 = __int_as_float(e0.y), ew1 = __int_as_float(e1.y);
        float ew2 = __int_as_float(e2.y), ew3 = __int_as_float(e3.y);

        float2 a0 = bfu2f(ku0.x), b0 = bfu2f(ku0.y);
        float2 a1 = bfu2f(ku1.x), b1 = bfu2f(ku1.y);
        float2 a2 = bfu2f(ku2.x), b2 = bfu2f(ku2.y);
        float2 a3 = bfu2f(ku3.x), b3 = bfu2f(ku3.y);
        float p40 = qv.x * a0.x + qv.y * a0.y + qv.z * b0.x + qv.w * b0.y;
        float p41 = qv.x * a1.x + qv.y * a1.y + qv.z * b1.x + qv.w * b1.y;
        float p42 = qv.x * a2.x + qv.y * a2.y + qv.z * b2.x + qv.w * b2.y;
        float p43 = qv.x * a3.x + qv.y * a3.y + qv.z * b3.x + qv.w * b3.y;
        p40 += __shfl_xor_sync(0xffffffffu, p40, 1);
        p41 += __shfl_xor_sync(0xffffffffu, p41, 1);
        p42 += __shfl_xor_sync(0xffffffffu, p42, 1);
        p43 += __shfl_xor_sync(0xffffffffu, p43, 1);
        p40 += __shfl_xor_sync(0xffffffffu, p40, 2);
        p41 += __shfl_xor_sync(0xffffffffu, p41, 2);
        p42 += __shfl_xor_sync(0xffffffffu, p42, 2);
        p43 += __shfl_xor_sync(0xffffffffu, p43, 2);
        p40 += __shfl_xor_sync(0xffffffffu, p40, 4);
        p41 += __shfl_xor_sync(0xffffffffu, p41, 4);
        p42 += __shfl_xor_sync(0xffffffffu, p42, 4);
        p43 += __shfl_xor_sync(0xffffffffu, p43, 4);
        float al0 = fmaf(ew0, qWe_h, p40) * INV_SQRT_C;
        float al1 = fmaf(ew1, qWe_h, p41) * INV_SQRT_C;
        float al2 = fmaf(ew2, qWe_h, p42) * INV_SQRT_C;
        float al3 = fmaf(ew3, qWe_h, p43) * INV_SQRT_C;

        float2 w0a = bfu2f(vu0.x), w0b = bfu2f(vu0.y);
        float2 w1a = bfu2f(vu1.x), w1b = bfu2f(vu1.y);
        float2 w2a = bfu2f(vu2.x), w2b = bfu2f(vu2.y);
        float2 w3a = bfu2f(vu3.x), w3b = bfu2f(vu3.y);
        online_update(al0, ew0, make_float4(w0a.x, w0a.y, w0b.x, w0b.y), wev, m, d, acc);
        online_update(al1, ew1, make_float4(w1a.x, w1a.y, w1b.x, w1b.y), wev, m, d, acc);
        online_update(al2, ew2, make_float4(w2a.x, w2a.y, w2b.x, w2b.y), wev, m, d, acc);
        online_update(al3, ew3, make_float4(w3a.x, w3a.y, w3b.x, w3b.y), wev, m, d, acc);
    }
    for (; j < end; ++j) {
        int2 e0 = g_se[j];
        float ew0 = __int_as_float(e0.y);
        uint2 ku0 = Kh[e0.x * 32 + lane];
        uint2 vu0 = Vh[e0.x * 32 + lane];
        float2 k0a = bfu2f(ku0.x), k0b = bfu2f(ku0.y);
        float p40 = qv.x * k0a.x + qv.y * k0a.y + qv.z * k0b.x + qv.w * k0b.y;
        p40 += __shfl_xor_sync(0xffffffffu, p40, 1);
        p40 += __shfl_xor_sync(0xffffffffu, p40, 2);
        p40 += __shfl_xor_sync(0xffffffffu, p40, 4);
        float al0 = fmaf(ew0, qWe_h, p40) * INV_SQRT_C;
        float2 v0a = bfu2f(vu0.x), v0b = bfu2f(vu0.y);
        online_update(al0, ew0, make_float4(v0a.x, v0a.y, v0b.x, v0b.y), wev, m, d, acc);
    }

    float invd = (d > 0.f) ? (1.f / d) : 0.f;
    float4* op = (float4*)out + node * 32 + lane;
    float4 cur = *op;
    cur.x += acc.x * invd;
    cur.y += acc.y * invd;
    cur.z += acc.z * invd;
    cur.w += acc.w * invd;
    *op = cur;
}

// ---------------- launch ---------------------------------------------------
// ncu's fixed window profiles MY 4th launch (2 harness launches precede).
// gemm1 is CSR-independent, so it is hoisted to position 4:
// init(1), hist(2), scanb(3), gemm1(4)<-profiled, scant(5), scana(6),
// scatter(7), edge1(8), gemm2(9), edge2(10).
extern "C" void kernel_launch(void* const* d_in, const int* in_sizes, int n_in,
                              void* d_out, int out_size)
{
    (void)in_sizes; (void)n_in; (void)out_size;
    const float* x    = (const float*)d_in[0];
    const float* ewt  = (const float*)d_in[1];
    const float* Wq1  = (const float*)d_in[2];
    const float* bq1  = (const float*)d_in[3];
    const float* Wk1  = (const float*)d_in[4];
    const float* bk1  = (const float*)d_in[5];
    const float* Wv1  = (const float*)d_in[6];
    const float* bv1  = (const float*)d_in[7];
    const float* We1  = (const float*)d_in[8];
    const float* Ws1  = (const float*)d_in[9];
    const float* bs1  = (const float*)d_in[10];
    const float* Wq2  = (const float*)d_in[11];
    const float* bq2  = (const float*)d_in[12];
    const float* Wk2  = (const float*)d_in[13];
    const float* bk2  = (const float*)d_in[14];
    const float* Wv2  = (const float*)d_in[15];
    const float* bv2  = (const float*)d_in[16];
    const float* We2  = (const float*)d_in[17];
    const float* Ws2  = (const float*)d_in[18];
    const float* bs2  = (const float*)d_in[19];
    const void* ei    = d_in[20];
    float* out = (float*)d_out;

    dim3 ggrid((NNODES + 127) / 128, 4);
    dim3 egrid((NNODES + 7) / 8);

    init_kernel<<<(NEDGES / 2 + 255) / 256, 256>>>((const unsigned int*)ei);
    hist_kernel<<<(NEDGES + 255) / 256, 256>>>(ei);
    scan_blocks_kernel<<<NSB, SB>>>();

    // gemm1 hoisted (CSR-independent) so it lands in the ncu window
    gemm4_fp16_kernel<<<ggrid, 256>>>(x, 0, Wq1, Wk1, Wv1, Ws1,
                                      bq1, bk1, bv1, bs1, nullptr, 1);

    scan_tops_kernel<<<1, 128>>>();
    scan_add_kernel<<<NSB, SB>>>();
    scatter_kernel<<<(NEDGES + 255) / 256, 256>>>(ei, ewt);

    edge_kernel<<<egrid, 256>>>(We1, nullptr, 1);

    // layer 2
    gemm4_fp16_kernel<<<ggrid, 256>>>(nullptr, 1, Wq2, Wk2, Wv2, Ws2,
                                      bq2, bk2, bv2, bs2, out, 0);
    edge_kernel<<<egrid, 256>>>(We2, out, 0);
}

// round 14
// speedup vs baseline: 1.4611x; 1.0504x over previous
#include <cuda_runtime.h>
#include <cuda_bf16.h>
#include <cuda_fp16.h>
#include <math.h>
#include <stdint.h>

#define NNODES 50000
#define NEDGES 800000
#define HC 128
#define INV_SQRT_C 0.1767766952966369f

#define SB 512
#define NSB ((NNODES + SB - 1) / SB)   // 98

// ---------------- scratch (device globals: allocation-free) ----------------
__device__ float          g_q[NNODES * HC];
__device__ __nv_bfloat16  g_kh[NNODES * HC];
__device__ __nv_bfloat16  g_vh[NNODES * HC];
__device__ float          g_h[NNODES * HC];
__device__ int   g_cnt[NNODES];
__device__ int   g_fill[NNODES];
__device__ int   g_rowptr[NNODES + 1];
__device__ int   g_bsum[NSB];
__device__ int2  g_se[NEDGES];      // packed (src, edge_weight-as-bits)
__device__ int   g_is32;            // 1 => edge_index is int32, 0 => int64

// ---------------- init: zero counts + dtype detection ----------------------
// If edge_index is int64 (values < 2^31), every odd 32-bit word in the first
// NEDGES words is a zero high-half. If int32, those words are random node ids.
__global__ void init_kernel(const unsigned int* __restrict__ w) {
    int i = blockIdx.x * blockDim.x + threadIdx.x;
    if (i < NNODES) { g_cnt[i] = 0; g_fill[i] = 0; }
    if (i == 0)     { g_is32 = 0; }
    int idx = 2 * i + 1;
    unsigned int nz = (idx < NEDGES && w[idx] != 0u) ? 1u : 0u;
    if (__ballot_sync(0xffffffffu, nz) && (threadIdx.x & 31) == 0)
        g_is32 = 1;
}

__device__ __forceinline__ int load_idx(const void* ei, int pos, int is32) {
    long long v;
    if (is32) v = ((const int*)ei)[pos];
    else      v = ((const long long*)ei)[pos];
    int iv = (int)v;
    if (iv < 0) iv = 0;
    if (iv >= NNODES) iv = NNODES - 1;
    return iv;
}

__global__ void hist_kernel(const void* __restrict__ ei) {
    int e = blockIdx.x * blockDim.x + threadIdx.x;
    if (e >= NEDGES) return;
    int is32 = g_is32;
    int d = load_idx(ei, NEDGES + e, is32);
    atomicAdd(&g_cnt[d], 1);
}

// ------- parallel prefix sum over g_cnt -> g_rowptr (3 small kernels) ------
__global__ void scan_blocks_kernel() {
    __shared__ int s[SB];
    int tid = threadIdx.x;
    int i = blockIdx.x * SB + tid;
    int v = (i < NNODES) ? g_cnt[i] : 0;
    s[tid] = v;
    __syncthreads();
    #pragma unroll
    for (int off = 1; off < SB; off <<= 1) {
        int t = (tid >= off) ? s[tid - off] : 0;
        __syncthreads();
        s[tid] += t;
        __syncthreads();
    }
    if (i < NNODES) g_rowptr[i + 1] = s[tid];
    if (tid == SB - 1) g_bsum[blockIdx.x] = s[tid];
}

__global__ void scan_tops_kernel() {   // 1 block, 128 threads, NSB<=128
    __shared__ int s[128];
    int tid = threadIdx.x;
    int v = (tid < NSB) ? g_bsum[tid] : 0;
    s[tid] = v;
    __syncthreads();
    #pragma unroll
    for (int off = 1; off < 128; off <<= 1) {
        int t = (tid >= off) ? s[tid - off] : 0;
        __syncthreads();
        s[tid] += t;
        __syncthreads();
    }
    if (tid < NSB) g_bsum[tid] = s[tid] - v;   // exclusive
}

__global__ void scan_add_kernel() {
    int i = blockIdx.x * SB + threadIdx.x;
    if (i < NNODES) g_rowptr[i + 1] += g_bsum[blockIdx.x];
    if (i == 0) g_rowptr[0] = 0;
}

__global__ void scatter_kernel(const void* __restrict__ ei,
                               const float* __restrict__ ew) {
    int e = blockIdx.x * blockDim.x + threadIdx.x;
    if (e >= NEDGES) return;
    int is32 = g_is32;
    int s = load_idx(ei, e, is32);
    int d = load_idx(ei, NEDGES + e, is32);
    int pos = g_rowptr[d] + atomicAdd(&g_fill[d], 1);
    g_se[pos] = make_int2(s, __float_as_int(ew[e]));
}

// ---------------- fused 4-way GEMM via fp16 mma m16n8k16 -------------------
// ONE CTA per 128-row tile computes ALL 4 matrices:
//  - A tile (full K=128) staged ONCE as fp16 in Asm[row][k2], row stride
//    AS=76 words (64 data + 12 pad): frag-load bank = r*12 + c, all 32
//    distinct -> conflict-free LDS for both k-halves.
//  - Serial loop over 4 W matrices; B double-buffered [k2][n] (GPAD=136,
//    conflict-free as before); acc registers reused per matrix.
#define GPAD 136
#define AS   76

__device__ __forceinline__ unsigned int h2u(float a, float b) {
    __half2 h = __floats2half2_rn(a, b);
    return *reinterpret_cast<unsigned int*>(&h);
}

__global__ __launch_bounds__(256, 2) void gemm4_fp16_kernel(
    const float* __restrict__ Xp, int xFromH,
    const float* __restrict__ Wq, const float* __restrict__ Wk,
    const float* __restrict__ Wv, const float* __restrict__ Ws,
    const float* __restrict__ bq, const float* __restrict__ bk,
    const float* __restrict__ bv, const float* __restrict__ bs,
    float* __restrict__ Op, int outToH)
{
    const float* X = xFromH ? g_h : Xp;

    __shared__ unsigned int Asm[128 * AS];       // fp16 A, full K resident
    __shared__ unsigned int Bs2[2][8][GPAD];     // fp16 B, double-buffered

    int tid  = threadIdx.x;
    int warp = tid >> 5;
    int lane = tid & 31;
    int r = lane >> 2;          // 0..7
    int c = lane & 3;           // 0..3
    int warp_m = (warp >> 2) * 64;
    int warp_n = (warp & 3) * 32;
    int mbase = blockIdx.x * 128;

    // ---- stage full A tile once: row = tid>>1, half = tid&1 (k 64*half..) --
    {
        const float4* Xv = (const float4*)X;
        int row  = tid >> 1;
        int half = tid & 1;
        int grow = mbase + row;
        bool ok = (grow < NNODES);
        #pragma unroll
        for (int i = 0; i < 4; i++) {
            float4 x0 = make_float4(0.f, 0.f, 0.f, 0.f), x1 = x0, x2 = x0, x3 = x0;
            if (ok) {
                const float4* base = Xv + grow * 32 + half * 16 + i * 4;
                x0 = base[0]; x1 = base[1]; x2 = base[2]; x3 = base[3];
            }
            uint4 u0 = make_uint4(h2u(x0.x, x0.y), h2u(x0.z, x0.w),
                                  h2u(x1.x, x1.y), h2u(x1.z, x1.w));
            uint4 u1 = make_uint4(h2u(x2.x, x2.y), h2u(x2.z, x2.w),
                                  h2u(x3.x, x3.y), h2u(x3.z, x3.w));
            unsigned int* dst = &Asm[row * AS + half * 32 + i * 8];
            *(uint4*)dst       = u0;
            *(uint4*)(dst + 4) = u1;
        }
    }
    __syncthreads();

    // B-load mapping: k2b = tid>>5 (0..7 -> k rows 2k2b, 2k2b+1), n4 = (tid&31)*4
    int k2b = tid >> 5;
    int n4  = (tid & 31) * 4;

    #pragma unroll
    for (int mm = 0; mm < 4; mm++) {
        const float* W; const float* B;
        float* O = nullptr;
        __nv_bfloat16* OH = nullptr;
        if      (mm == 0) { W = Wq; B = bq; O = g_q; }
        else if (mm == 1) { W = Wk; B = bk; OH = g_kh; }
        else if (mm == 2) { W = Wv; B = bv; OH = g_vh; }
        else              { W = Ws; B = bs; O = outToH ? g_h : Op; }

        float acc[4][4][4];
        #pragma unroll
        for (int mi = 0; mi < 4; mi++)
            #pragma unroll
            for (int ni = 0; ni < 4; ni++)
                #pragma unroll
                for (int q = 0; q < 4; q++) acc[mi][ni][q] = 0.f;

        float4 rb0, rb1;
        // prologue: B tile 0
        rb0 = *(const float4*)(W + (2 * k2b)     * 128 + n4);
        rb1 = *(const float4*)(W + (2 * k2b + 1) * 128 + n4);
        {
            uint4 bu = make_uint4(h2u(rb0.x, rb1.x), h2u(rb0.y, rb1.y),
                                  h2u(rb0.z, rb1.z), h2u(rb0.w, rb1.w));
            *(uint4*)&Bs2[0][k2b][n4] = bu;
        }
        __syncthreads();

        #pragma unroll
        for (int kt = 0; kt < 8; kt++) {
            int cur = kt & 1;
            int nxt = cur ^ 1;
            if (kt < 7) {
                int k0 = (kt + 1) * 16;
                rb0 = *(const float4*)(W + (k0 + 2 * k2b)     * 128 + n4);
                rb1 = *(const float4*)(W + (k0 + 2 * k2b + 1) * 128 + n4);
            }
            {
                unsigned int af[4][4];
                #pragma unroll
                for (int mi = 0; mi < 4; mi++) {
                    int r0 = (warp_m + mi * 16 + r) * AS + kt * 8 + c;
                    int r1 = r0 + 8 * AS;
                    af[mi][0] = Asm[r0];
                    af[mi][1] = Asm[r1];
                    af[mi][2] = Asm[r0 + 4];
                    af[mi][3] = Asm[r1 + 4];
                }
                unsigned int bf[4][2];
                #pragma unroll
                for (int ni = 0; ni < 4; ni++) {
                    int bn = warp_n + ni * 8;
                    bf[ni][0] = Bs2[cur][c][bn + r];
                    bf[ni][1] = Bs2[cur][c + 4][bn + r];
                }
                #pragma unroll
                for (int mi = 0; mi < 4; mi++)
                    #pragma unroll
                    for (int ni = 0; ni < 4; ni++) {
                        asm volatile(
                            "mma.sync.aligned.m16n8k16.row.col.f32.f16.f16.f32 "
                            "{%0,%1,%2,%3}, {%4,%5,%6,%7}, {%8,%9}, {%0,%1,%2,%3};"
                            : "+f"(acc[mi][ni][0]), "+f"(acc[mi][ni][1]),
                              "+f"(acc[mi][ni][2]), "+f"(acc[mi][ni][3])
                            : "r"(af[mi][0]), "r"(af[mi][1]),
                              "r"(af[mi][2]), "r"(af[mi][3]),
                              "r"(bf[ni][0]), "r"(bf[ni][1]));
                    }
            }
            if (kt < 7) {
                uint4 bu = make_uint4(h2u(rb0.x, rb1.x), h2u(rb0.y, rb1.y),
                                      h2u(rb0.z, rb1.z), h2u(rb0.w, rb1.w));
                *(uint4*)&Bs2[nxt][k2b][n4] = bu;
            }
            __syncthreads();
        }

        // ---- epilogue: + bias, store (fp32 for q/skip, bf16 for k/v) ----
        #pragma unroll
        for (int ni = 0; ni < 4; ni++) {
            int col = warp_n + ni * 8 + c * 2;
            float b0 = B[col];
            float b1 = B[col + 1];
            #pragma unroll
            for (int mi = 0; mi < 4; mi++) {
                int row0 = mbase + warp_m + mi * 16 + r;
                int row1 = row0 + 8;
                if (OH) {
                    if (row0 < NNODES)
                        ((__nv_bfloat162*)OH)[row0 * 64 + col / 2] =
                            __float22bfloat162_rn(make_float2(acc[mi][ni][0] + b0,
                                                              acc[mi][ni][1] + b1));
                    if (row1 < NNODES)
                        ((__nv_bfloat162*)OH)[row1 * 64 + col / 2] =
                            __float22bfloat162_rn(make_float2(acc[mi][ni][2] + b0,
                                                              acc[mi][ni][3] + b1));
                } else {
                    if (row0 < NNODES) {
                        float2 o = make_float2(acc[mi][ni][0] + b0, acc[mi][ni][1] + b1);
                        *(float2*)&O[row0 * 128 + col] = o;
                    }
                    if (row1 < NNODES) {
                        float2 o = make_float2(acc[mi][ni][2] + b0, acc[mi][ni][3] + b1);
                        *(float2*)&O[row1 * 128 + col] = o;
                    }
                }
            }
        }
    }
}

// ---------------- edge aggregation (R9 form): warp/node, online softmax ----
__device__ __forceinline__ float2 bfu2f(unsigned int u) {
    __nv_bfloat162 b = *reinterpret_cast<__nv_bfloat162*>(&u);
    return __bfloat1622float2(b);
}

__device__ __forceinline__ void online_update(
    float alpha, float ew, const float4& vv, const float4& wev,
    float& m, float& d, float4& acc)
{
    float delta = alpha - m;
    float e = __expf(0.f - fabsf(delta));
    bool up = delta > 0.f;
    float p    = up ? 1.f : e;
    float corr = up ? e : 1.f;
    m = fmaxf(m, alpha);
    d = fmaf(d, corr, p);
    float vjx = fmaf(ew, wev.x, vv.x);
    float vjy = fmaf(ew, wev.y, vv.y);
    float vjz = fmaf(ew, wev.z, vv.z);
    float vjw = fmaf(ew, wev.w, vv.w);
    acc.x = fmaf(p, vjx, acc.x * corr);
    acc.y = fmaf(p, vjy, acc.y * corr);
    acc.z = fmaf(p, vjz, acc.z * corr);
    acc.w = fmaf(p, vjw, acc.w * corr);
}

__global__ __launch_bounds__(256) void edge_kernel(
    const float* __restrict__ We, float* __restrict__ Op, int outToH)
{
    float* out = outToH ? g_h : Op;
    int node = blockIdx.x * 8 + (threadIdx.x >> 5);
    if (node >= NNODES) return;
    int lane = threadIdx.x & 31;

    float4 qv  = ((const float4*)g_q)[node * 32 + lane];
    float4 wev = ((const float4*)We)[lane];

    float t = qv.x * wev.x + qv.y * wev.y + qv.z * wev.z + qv.w * wev.w;
    t += __shfl_xor_sync(0xffffffffu, t, 1);
    t += __shfl_xor_sync(0xffffffffu, t, 2);
    t += __shfl_xor_sync(0xffffffffu, t, 4);
    float qWe_h = t;

    const uint2* Kh = (const uint2*)g_kh;
    const uint2* Vh = (const uint2*)g_vh;

    int beg = g_rowptr[node];
    int end = g_rowptr[node + 1];

    float m = -3.0e38f;
    float d = 0.f;
    float4 acc = make_float4(0.f, 0.f, 0.f, 0.f);

    int j = beg;
    int n4 = beg + ((end - beg) & ~3);
    for (; j < n4; j += 4) {
        int2 e0 = g_se[j],     e1 = g_se[j + 1];
        int2 e2 = g_se[j + 2], e3 = g_se[j + 3];
        uint2 ku0 = Kh[e0.x * 32 + lane], ku1 = Kh[e1.x * 32 + lane];
        uint2 ku2 = Kh[e2.x * 32 + lane], ku3 = Kh[e3.x * 32 + lane];
        uint2 vu0 = Vh[e0.x * 32 + lane], vu1 = Vh[e1.x * 32 + lane];
        uint2 vu2 = Vh[e2.x * 32 + lane], vu3 = Vh[e3.x * 32 + lane];
        float ew0 = __int_as_float(e0.y), ew1 = __int_as_float(e1.y);
        float ew2 = __int_as_float(e2.y), ew3 = __int_as_float(e3.y);

        float2 a0 = bfu2f(ku0.x), b0 = bfu2f(ku0.y);
        float2 a1 = bfu2f(ku1.x), b1 = bfu2f(ku1.y);
        float2 a2 = bfu2f(ku2.x), b2 = bfu2f(ku2.y);
        float2 a3 = bfu2f(ku3.x), b3 = bfu2f(ku3.y);
        float p40 = qv.x * a0.x + qv.y * a0.y + qv.z * b0.x + qv.w * b0.y;
        float p41 = qv.x * a1.x + qv.y * a1.y + qv.z * b1.x + qv.w * b1.y;
        float p42 = qv.x * a2.x + qv.y * a2.y + qv.z * b2.x + qv.w * b2.y;
        float p43 = qv.x * a3.x + qv.y * a3.y + qv.z * b3.x + qv.w * b3.y;
        p40 += __shfl_xor_sync(0xffffffffu, p40, 1);
        p41 += __shfl_xor_sync(0xffffffffu, p41, 1);
        p42 += __shfl_xor_sync(0xffffffffu, p42, 1);
        p43 += __shfl_xor_sync(0xffffffffu, p43, 1);
        p40 += __shfl_xor_sync(0xffffffffu, p40, 2);
        p41 += __shfl_xor_sync(0xffffffffu, p41, 2);
        p42 += __shfl_xor_sync(0xffffffffu, p42, 2);
        p43 += __shfl_xor_sync(0xffffffffu, p43, 2);
        p40 += __shfl_xor_sync(0xffffffffu, p40, 4);
        p41 += __shfl_xor_sync(0xffffffffu, p41, 4);
        p42 += __shfl_xor_sync(0xffffffffu, p42, 4);
        p43 += __shfl_xor_sync(0xffffffffu, p43, 4);
        float al0 = fmaf(ew0, qWe_h, p40) * INV_SQRT_C;
        float al1 = fmaf(ew1, qWe_h, p41) * INV_SQRT_C;
        float al2 = fmaf(ew2, qWe_h, p42) * INV_SQRT_C;
        float al3 = fmaf(ew3, qWe_h, p43) * INV_SQRT_C;

        float2 w0a = bfu2f(vu0.x), w0b = bfu2f(vu0.y);
        float2 w1a = bfu2f(vu1.x), w1b = bfu2f(vu1.y);
        float2 w2a = bfu2f(vu2.x), w2b = bfu2f(vu2.y);
        float2 w3a = bfu2f(vu3.x), w3b = bfu2f(vu3.y);
        online_update(al0, ew0, make_float4(w0a.x, w0a.y, w0b.x, w0b.y), wev, m, d, acc);
        online_update(al1, ew1, make_float4(w1a.x, w1a.y, w1b.x, w1b.y), wev, m, d, acc);
        online_update(al2, ew2, make_float4(w2a.x, w2a.y, w2b.x, w2b.y), wev, m, d, acc);
        online_update(al3, ew3, make_float4(w3a.x, w3a.y, w3b.x, w3b.y), wev, m, d, acc);
    }
    for (; j < end; ++j) {
        int2 e0 = g_se[j];
        float ew0 = __int_as_float(e0.y);
        uint2 ku0 = Kh[e0.x * 32 + lane];
        uint2 vu0 = Vh[e0.x * 32 + lane];
        float2 k0a = bfu2f(ku0.x), k0b = bfu2f(ku0.y);
        float p40 = qv.x * k0a.x + qv.y * k0a.y + qv.z * k0b.x + qv.w * k0b.y;
        p40 += __shfl_xor_sync(0xffffffffu, p40, 1);
        p40 += __shfl_xor_sync(0xffffffffu, p40, 2);
        p40 += __shfl_xor_sync(0xffffffffu, p40, 4);
        float al0 = fmaf(ew0, qWe_h, p40) * INV_SQRT_C;
        float2 v0a = bfu2f(vu0.x), v0b = bfu2f(vu0.y);
        online_update(al0, ew0, make_float4(v0a.x, v0a.y, v0b.x, v0b.y), wev, m, d, acc);
    }

    float invd = (d > 0.f) ? (1.f / d) : 0.f;
    float4* op = (float4*)out + node * 32 + lane;
    float4 cur = *op;
    cur.x += acc.x * invd;
    cur.y += acc.y * invd;
    cur.z += acc.z * invd;
    cur.w += acc.w * invd;
    *op = cur;
}

// ---------------- launch ---------------------------------------------------
// ncu's fixed window profiles MY 4th launch; gemm1 stays there to verify the
// restructure: init(1), hist(2), scanb(3), gemm1(4)<-profiled, scant(5),
// scana(6), scatter(7), edge1(8), gemm2(9), edge2(10).
extern "C" void kernel_launch(void* const* d_in, const int* in_sizes, int n_in,
                              void* d_out, int out_size)
{
    (void)in_sizes; (void)n_in; (void)out_size;
    const float* x    = (const float*)d_in[0];
    const float* ewt  = (const float*)d_in[1];
    const float* Wq1  = (const float*)d_in[2];
    const float* bq1  = (const float*)d_in[3];
    const float* Wk1  = (const float*)d_in[4];
    const float* bk1  = (const float*)d_in[5];
    const float* Wv1  = (const float*)d_in[6];
    const float* bv1  = (const float*)d_in[7];
    const float* We1  = (const float*)d_in[8];
    const float* Ws1  = (const float*)d_in[9];
    const float* bs1  = (const float*)d_in[10];
    const float* Wq2  = (const float*)d_in[11];
    const float* bq2  = (const float*)d_in[12];
    const float* Wk2  = (const float*)d_in[13];
    const float* bk2  = (const float*)d_in[14];
    const float* Wv2  = (const float*)d_in[15];
    const float* bv2  = (const float*)d_in[16];
    const float* We2  = (const float*)d_in[17];
    const float* Ws2  = (const float*)d_in[18];
    const float* bs2  = (const float*)d_in[19];
    const void* ei    = d_in[20];
    float* out = (float*)d_out;

    dim3 ggrid((NNODES + 127) / 128);
    dim3 egrid((NNODES + 7) / 8);

    init_kernel<<<(NEDGES / 2 + 255) / 256, 256>>>((const unsigned int*)ei);
    hist_kernel<<<(NEDGES + 255) / 256, 256>>>(ei);
    scan_blocks_kernel<<<NSB, SB>>>();

    // gemm1 hoisted (CSR-independent) so it lands in the ncu window
    gemm4_fp16_kernel<<<ggrid, 256>>>(x, 0, Wq1, Wk1, Wv1, Ws1,
                                      bq1, bk1, bv1, bs1, nullptr, 1);

    scan_tops_kernel<<<1, 128>>>();
    scan_add_kernel<<<NSB, SB>>>();
    scatter_kernel<<<(NEDGES + 255) / 256, 256>>>(ei, ewt);

    edge_kernel<<<egrid, 256>>>(We1, nullptr, 1);

    // layer 2
    gemm4_fp16_kernel<<<ggrid, 256>>>(nullptr, 1, Wq2, Wk2, Wv2, Ws2,
                                      bq2, bk2, bv2, bs2, out, 0);
    edge_kernel<<<egrid, 256>>>(We2, out, 0);
}